// round 3
// baseline (speedup 1.0000x reference)
#include <cuda_runtime.h>
#include <cuda_bf16.h>
#include <math.h>

// ---------------- problem constants ----------------
#define QL 512
#define ML 512
#define KL 1024          // QL + ML
#define BSZ 4
#define NH 16
#define DH 64
#define DM 1024
#define DI 4096
#define NV 32000
#define NL 6
#define HD3 3072         // 3*NH*DH

// ---------------- scratch (static device memory; no allocation) ----------------
__device__ float g_h[(size_t)QL * BSZ * DM];          // 8 MB
__device__ float g_cat[(size_t)KL * BSZ * DM];        // 16 MB
__device__ float g_heads[(size_t)KL * BSZ * HD3];     // 50 MB
__device__ float g_pos[(size_t)KL * DM];              // 4 MB
__device__ float g_r[(size_t)KL * DM];                // 4 MB
__device__ float g_av[(size_t)QL * BSZ * DM];         // 8 MB
__device__ float g_ao[(size_t)QL * BSZ * DM];         // 8 MB
__device__ float g_ffh[(size_t)QL * BSZ * DI];        // 33 MB
__device__ float g_ff[(size_t)QL * BSZ * DM];         // 8 MB
__device__ float g_logits[(size_t)QL * BSZ * NV];     // 262 MB

// ---------------- positional embedding ----------------
__global__ void posemb_kernel(float* __restrict__ pos) {
    int p = blockIdx.x;          // 0..KL-1
    int j = threadIdx.x;         // 0..511
    float posv = (float)(KL - 1 - p);
    float inv = expf(-(float)(2 * j) * (9.210340371976184f / 1024.0f));
    float a = posv * inv;
    pos[(size_t)p * DM + j]       = sinf(a);
    pos[(size_t)p * DM + 512 + j] = cosf(a);
}

// ---------------- embedding lookup ----------------
__global__ void embed_kernel(const int* __restrict__ data,
                             const float* __restrict__ emb,
                             float* __restrict__ h) {
    int row = blockIdx.x;        // i*BSZ + b, 0..2047
    int tok = data[row];
    const float4* src = (const float4*)(emb + (size_t)tok * DM);
    float4* dst = (float4*)(h + (size_t)row * DM);
    int d = threadIdx.x;         // 256 threads -> 256 float4 = 1024 floats
    float4 f = src[d];
    f.x *= 32.0f; f.y *= 32.0f; f.z *= 32.0f; f.w *= 32.0f;  // sqrt(1024)
    dst[d] = f;
}

// ---------------- concat [mems_l ; h] -> cat ----------------
__global__ void concat_kernel(const float* __restrict__ mems_l,
                              const float* __restrict__ h,
                              float* __restrict__ cat) {
    int row = blockIdx.x;        // kl*BSZ + b, 0..4095
    const float4* src = (row < ML * BSZ)
        ? (const float4*)(mems_l + (size_t)row * DM)
        : (const float4*)(h + (size_t)(row - ML * BSZ) * DM);
    float4* dst = (float4*)(cat + (size_t)row * DM);
    dst[threadIdx.x] = src[threadIdx.x];
}

// ---------------- tiled SGEMM: C[m,n] = sum_k A[m,k]*B[n,k] (+bias)(relu) ----------------
// BM=BN=128, BK=16, 256 threads, 8x8 accum, register-prefetch pipeline.
// M,N multiples of 128; K multiple of 16. EPI: 0=none, 1=+bias, 2=+bias,relu
template <int EPI>
__global__ void __launch_bounds__(256)
sgemm_nt(const float* __restrict__ A, const float* __restrict__ B,
         const float* __restrict__ bias, float* __restrict__ C,
         int M, int N, int K) {
    __shared__ __align__(16) float As[16][128];
    __shared__ __align__(16) float Bs[16][128];
    int bm = blockIdx.x * 128;
    int bn = blockIdx.y * 128;
    int tid = threadIdx.x;
    int tm = (tid / 16) * 8;
    int tn = (tid % 16) * 8;

    int idx0 = tid;            // first float4 of the 128x16 tile
    int idx1 = tid + 256;      // second float4
    int row0 = idx0 >> 2, c40 = idx0 & 3;
    int row1 = idx1 >> 2, c41 = idx1 & 3;
    const float* Ab = A + (size_t)bm * K;
    const float* Bb = B + (size_t)bn * K;

    float acc[8][8];
#pragma unroll
    for (int i = 0; i < 8; i++)
#pragma unroll
        for (int j = 0; j < 8; j++) acc[i][j] = 0.0f;

    // prefetch k0 = 0
    float4 pa0 = *(const float4*)(Ab + (size_t)row0 * K + c40 * 4);
    float4 pa1 = *(const float4*)(Ab + (size_t)row1 * K + c41 * 4);
    float4 pb0 = *(const float4*)(Bb + (size_t)row0 * K + c40 * 4);
    float4 pb1 = *(const float4*)(Bb + (size_t)row1 * K + c41 * 4);

    for (int k0 = 0; k0 < K; k0 += 16) {
        As[c40 * 4 + 0][row0] = pa0.x; As[c40 * 4 + 1][row0] = pa0.y;
        As[c40 * 4 + 2][row0] = pa0.z; As[c40 * 4 + 3][row0] = pa0.w;
        As[c41 * 4 + 0][row1] = pa1.x; As[c41 * 4 + 1][row1] = pa1.y;
        As[c41 * 4 + 2][row1] = pa1.z; As[c41 * 4 + 3][row1] = pa1.w;
        Bs[c40 * 4 + 0][row0] = pb0.x; Bs[c40 * 4 + 1][row0] = pb0.y;
        Bs[c40 * 4 + 2][row0] = pb0.z; Bs[c40 * 4 + 3][row0] = pb0.w;
        Bs[c41 * 4 + 0][row1] = pb1.x; Bs[c41 * 4 + 1][row1] = pb1.y;
        Bs[c41 * 4 + 2][row1] = pb1.z; Bs[c41 * 4 + 3][row1] = pb1.w;
        __syncthreads();

        int kn = k0 + 16;
        if (kn < K) {
            pa0 = *(const float4*)(Ab + (size_t)row0 * K + kn + c40 * 4);
            pa1 = *(const float4*)(Ab + (size_t)row1 * K + kn + c41 * 4);
            pb0 = *(const float4*)(Bb + (size_t)row0 * K + kn + c40 * 4);
            pb1 = *(const float4*)(Bb + (size_t)row1 * K + kn + c41 * 4);
        }

#pragma unroll
        for (int kk = 0; kk < 16; kk++) {
            float4 a0 = *(const float4*)&As[kk][tm];
            float4 a1 = *(const float4*)&As[kk][tm + 4];
            float4 b0 = *(const float4*)&Bs[kk][tn];
            float4 b1 = *(const float4*)&Bs[kk][tn + 4];
            float ra[8] = {a0.x, a0.y, a0.z, a0.w, a1.x, a1.y, a1.z, a1.w};
            float rb[8] = {b0.x, b0.y, b0.z, b0.w, b1.x, b1.y, b1.z, b1.w};
#pragma unroll
            for (int i = 0; i < 8; i++)
#pragma unroll
                for (int j = 0; j < 8; j++) acc[i][j] = fmaf(ra[i], rb[j], acc[i][j]);
        }
        __syncthreads();
    }
#pragma unroll
    for (int i = 0; i < 8; i++) {
        size_t m = (size_t)(bm + tm + i);
#pragma unroll
        for (int j = 0; j < 8; j++) {
            int n = bn + tn + j;
            float v = acc[i][j];
            if (EPI >= 1) v += bias[n];
            if (EPI == 2) v = fmaxf(v, 0.0f);
            C[m * N + n] = v;
        }
    }
}

// ---------------- fused relative attention ----------------
// block (i, b*NH+n), 128 threads. Computes softmax((q+rwb)·k + (q+rrb)·r_shift)·v
__global__ void __launch_bounds__(128)
attn_kernel(const float* __restrict__ heads, const float* __restrict__ r,
            const float* __restrict__ rwb, const float* __restrict__ rrb,
            float* __restrict__ out) {
    int i = blockIdx.x;
    int b = blockIdx.y >> 4;
    int n = blockIdx.y & 15;
    int tid = threadIdx.x;

    __shared__ __align__(16) float qc[64];
    __shared__ __align__(16) float qr[64];
    __shared__ float sc[KL];
    __shared__ float red[128];

    const float* qrow = heads + ((size_t)(ML + i) * BSZ + b) * HD3 + n * DH;
    if (tid < 64) {
        float qv = qrow[tid];
        qc[tid] = qv + rwb[n * DH + tid];
        qr[tid] = qv + rrb[n * DH + tid];
    }
    __syncthreads();

    int jmax = i + ML;  // inclusive; j > jmax is masked
    const float* kbase = heads + (size_t)b * HD3 + NH * DH + n * DH;  // + j*BSZ*HD3
    const float4* qc4 = (const float4*)qc;
    const float4* qr4 = (const float4*)qr;

    float lmax = -1e30f;
    for (int j = tid; j <= jmax; j += 128) {
        const float4* k4 = (const float4*)(kbase + (size_t)j * BSZ * HD3);
        const float4* r4 = (const float4*)(r + (size_t)(j - i + QL - 1) * DM + n * DH);
        float s = 0.0f;
#pragma unroll
        for (int d = 0; d < 16; d++) {
            float4 kk = k4[d], rr = r4[d], q1 = qc4[d], q2 = qr4[d];
            s += q1.x * kk.x + q1.y * kk.y + q1.z * kk.z + q1.w * kk.w;
            s += q2.x * rr.x + q2.y * rr.y + q2.z * rr.z + q2.w * rr.w;
        }
        s *= 0.125f;  // 1/sqrt(64)
        sc[j] = s;
        lmax = fmaxf(lmax, s);
    }
    red[tid] = lmax;
    __syncthreads();
    for (int t = 64; t > 0; t >>= 1) {
        if (tid < t) red[tid] = fmaxf(red[tid], red[tid + t]);
        __syncthreads();
    }
    float m = red[0];
    __syncthreads();

    float lsum = 0.0f;
    for (int j = tid; j <= jmax; j += 128) {
        float e = expf(sc[j] - m);
        sc[j] = e;
        lsum += e;
    }
    red[tid] = lsum;
    __syncthreads();
    for (int t = 64; t > 0; t >>= 1) {
        if (tid < t) red[tid] += red[tid + t];
        __syncthreads();
    }
    float inv = 1.0f / red[0];
    __syncthreads();

    int d = tid & 63;
    int half = tid >> 6;
    const float* vbase = heads + (size_t)b * HD3 + 2 * NH * DH + n * DH + d;
    float acc = 0.0f;
    for (int j = half; j <= jmax; j += 2)
        acc += sc[j] * vbase[(size_t)j * BSZ * HD3];
    red[tid] = acc;
    __syncthreads();
    if (tid < 64)
        out[((size_t)i * BSZ + b) * DM + n * DH + tid] = (red[tid] + red[tid + 64]) * inv;
}

// ---------------- fused residual + layernorm ----------------
__global__ void __launch_bounds__(256)
ln_kernel(const float* __restrict__ x, const float* __restrict__ y,
          const float* __restrict__ g, const float* __restrict__ b,
          float* __restrict__ out) {
    int row = blockIdx.x;  // 0..2047
    __shared__ float buf[DM];
    __shared__ float red[256];
    int tid = threadIdx.x;
    float s = 0.0f;
    for (int d = tid; d < DM; d += 256) {
        float v = x[(size_t)row * DM + d] + y[(size_t)row * DM + d];
        buf[d] = v;
        s += v;
    }
    red[tid] = s;
    __syncthreads();
    for (int t = 128; t > 0; t >>= 1) {
        if (tid < t) red[tid] += red[tid + t];
        __syncthreads();
    }
    float mu = red[0] * (1.0f / DM);
    __syncthreads();
    float s2 = 0.0f;
    for (int d = tid; d < DM; d += 256) {
        float v = buf[d] - mu;
        s2 += v * v;
    }
    red[tid] = s2;
    __syncthreads();
    for (int t = 128; t > 0; t >>= 1) {
        if (tid < t) red[tid] += red[tid + t];
        __syncthreads();
    }
    float rstd = rsqrtf(red[0] * (1.0f / DM) + 1e-5f);
    __syncthreads();
    for (int d = tid; d < DM; d += 256)
        out[(size_t)row * DM + d] = (buf[d] - mu) * rstd * g[d] + b[d];
}

// ---------------- streaming log-softmax NLL ----------------
__global__ void __launch_bounds__(256)
loss_kernel(const float* __restrict__ logits, const int* __restrict__ target,
            float* __restrict__ out) {
    int row = blockIdx.x;  // i*BSZ + b
    const float* lr = logits + (size_t)row * NV;
    __shared__ float red[256];
    int tid = threadIdx.x;
    float m = -1e30f;
    for (int v = tid; v < NV; v += 256) m = fmaxf(m, lr[v]);
    red[tid] = m;
    __syncthreads();
    for (int t = 128; t > 0; t >>= 1) {
        if (tid < t) red[tid] = fmaxf(red[tid], red[tid + t]);
        __syncthreads();
    }
    float M = red[0];
    __syncthreads();
    float s = 0.0f;
    for (int v = tid; v < NV; v += 256) s += expf(lr[v] - M);
    red[tid] = s;
    __syncthreads();
    for (int t = 128; t > 0; t >>= 1) {
        if (tid < t) red[tid] += red[tid + t];
        __syncthreads();
    }
    if (tid == 0) {
        int t = target[row];
        out[row] = -(lr[t] - M - logf(red[0]));
    }
}

// ---------------- driver ----------------
extern "C" void kernel_launch(void* const* d_in, const int* in_sizes, int n_in,
                              void* d_out, int out_size) {
    const int*   data     = (const int*)d_in[0];
    const int*   target   = (const int*)d_in[1];
    const float* mems     = (const float*)d_in[2];
    const float* emb      = (const float*)d_in[3];
    const float* out_bias = (const float*)d_in[4];
    const float* rwb      = (const float*)d_in[5];
    const float* rrb      = (const float*)d_in[6];
    const float* qkv_w    = (const float*)d_in[7];
    const float* r_w      = (const float*)d_in[8];
    const float* o_w      = (const float*)d_in[9];
    const float* ln1g     = (const float*)d_in[10];
    const float* ln1b     = (const float*)d_in[11];
    const float* ff1w     = (const float*)d_in[12];
    const float* ff1b     = (const float*)d_in[13];
    const float* ff2w     = (const float*)d_in[14];
    const float* ff2b     = (const float*)d_in[15];
    const float* ln2g     = (const float*)d_in[16];
    const float* ln2b     = (const float*)d_in[17];
    float* out = (float*)d_out;

    // resolved fresh on every call — no static state, deterministic
    float *p_h, *p_cat, *p_heads, *p_pos, *p_r, *p_av, *p_ao, *p_ffh, *p_ff, *p_logits;
    cudaGetSymbolAddress((void**)&p_h, g_h);
    cudaGetSymbolAddress((void**)&p_cat, g_cat);
    cudaGetSymbolAddress((void**)&p_heads, g_heads);
    cudaGetSymbolAddress((void**)&p_pos, g_pos);
    cudaGetSymbolAddress((void**)&p_r, g_r);
    cudaGetSymbolAddress((void**)&p_av, g_av);
    cudaGetSymbolAddress((void**)&p_ao, g_ao);
    cudaGetSymbolAddress((void**)&p_ffh, g_ffh);
    cudaGetSymbolAddress((void**)&p_ff, g_ff);
    cudaGetSymbolAddress((void**)&p_logits, g_logits);

    posemb_kernel<<<KL, 512>>>(p_pos);
    embed_kernel<<<QL * BSZ, 256>>>(data, emb, p_h);

    for (int l = 0; l < NL; l++) {
        concat_kernel<<<KL * BSZ, 256>>>(mems + (size_t)l * ML * BSZ * DM, p_h, p_cat);
        // heads = cat @ qkv_w[l]^T : M=4096, N=3072, K=1024
        sgemm_nt<0><<<dim3(32, 24), 256>>>(p_cat, qkv_w + (size_t)l * HD3 * DM,
                                           nullptr, p_heads, KL * BSZ, HD3, DM);
        // r = pos_emb @ r_w[l]^T : M=1024, N=1024, K=1024
        sgemm_nt<0><<<dim3(8, 8), 256>>>(p_pos, r_w + (size_t)l * DM * DM,
                                         nullptr, p_r, KL, DM, DM);
        attn_kernel<<<dim3(QL, BSZ * NH), 128>>>(p_heads, p_r, rwb, rrb, p_av);
        // attn_out = attn_vec @ o_w[l]^T : M=2048, N=1024, K=1024
        sgemm_nt<0><<<dim3(16, 8), 256>>>(p_av, o_w + (size_t)l * DM * DM,
                                          nullptr, p_ao, QL * BSZ, DM, DM);
        ln_kernel<<<QL * BSZ, 256>>>(p_h, p_ao, ln1g + l * DM, ln1b + l * DM, p_h);
        // ff_h = relu(h @ ff1_w^T + b) : M=2048, N=4096, K=1024
        sgemm_nt<2><<<dim3(16, 32), 256>>>(p_h, ff1w + (size_t)l * DI * DM,
                                           ff1b + (size_t)l * DI, p_ffh, QL * BSZ, DI, DM);
        // ff = ff_h @ ff2_w^T + b : M=2048, N=1024, K=4096
        sgemm_nt<1><<<dim3(16, 8), 256>>>(p_ffh, ff2w + (size_t)l * DM * DI,
                                          ff2b + (size_t)l * DM, p_ff, QL * BSZ, DM, DI);
        ln_kernel<<<QL * BSZ, 256>>>(p_h, p_ff, ln2g + l * DM, ln2b + l * DM, p_h);
    }

    // logits = h @ emb^T + out_bias : M=2048, N=32000, K=1024
    sgemm_nt<1><<<dim3(16, 250), 256>>>(p_h, emb, out_bias, p_logits, QL * BSZ, NV, DM);
    loss_kernel<<<QL * BSZ, 256>>>(p_logits, target, out);
}

// round 6
// speedup vs baseline: 2.3703x; 2.3703x over previous
#include <cuda_runtime.h>
#include <cuda_bf16.h>
#include <mma.h>
#include <math.h>

using namespace nvcuda;

// ---------------- problem constants ----------------
#define QL 512
#define ML 512
#define KL 1024          // QL + ML
#define BSZ 4
#define NH 16
#define DH 64
#define DM 1024
#define DI 4096
#define NV 32000
#define NL 6
#define HD3 3072         // 3*NH*DH

// ---------------- scratch (static device memory; no allocation) ----------------
__device__ float g_h[(size_t)QL * BSZ * DM];          // 8 MB
__device__ float g_cat[(size_t)KL * BSZ * DM];        // 16 MB
__device__ float g_heads[(size_t)KL * BSZ * HD3];     // 50 MB
__device__ float g_pos[(size_t)KL * DM];              // 4 MB
__device__ float g_r[(size_t)KL * DM];                // 4 MB
__device__ float g_qc[(size_t)BSZ * NH * QL * DH];    // 8 MB   [n*4+b][i][d]
__device__ float g_qr[(size_t)BSZ * NH * QL * DH];    // 8 MB
__device__ float g_S[(size_t)BSZ * NH * QL * KL];     // 134 MB [n*4+b][i][j]  (AC, then P)
__device__ float g_D[(size_t)BSZ * NH * QL * KL];     // 134 MB
__device__ float g_av[(size_t)QL * BSZ * DM];         // 8 MB
__device__ float g_ao[(size_t)QL * BSZ * DM];         // 8 MB
__device__ float g_ffh[(size_t)QL * BSZ * DI];        // 33 MB
__device__ float g_ff[(size_t)QL * BSZ * DM];         // 8 MB
__device__ float g_logits[(size_t)QL * BSZ * NV];     // 262 MB

// ---------------- positional embedding ----------------
__global__ void posemb_kernel(float* __restrict__ pos) {
    int p = blockIdx.x;          // 0..KL-1
    int j = threadIdx.x;         // 0..511
    float posv = (float)(KL - 1 - p);
    float inv = expf(-(float)(2 * j) * (9.210340371976184f / 1024.0f));
    float a = posv * inv;
    pos[(size_t)p * DM + j]       = sinf(a);
    pos[(size_t)p * DM + 512 + j] = cosf(a);
}

// ---------------- embedding lookup ----------------
__global__ void embed_kernel(const int* __restrict__ data,
                             const float* __restrict__ emb,
                             float* __restrict__ h) {
    int row = blockIdx.x;        // i*BSZ + b
    int tok = data[row];
    const float4* src = (const float4*)(emb + (size_t)tok * DM);
    float4* dst = (float4*)(h + (size_t)row * DM);
    int d = threadIdx.x;
    float4 f = src[d];
    f.x *= 32.0f; f.y *= 32.0f; f.z *= 32.0f; f.w *= 32.0f;  // sqrt(1024)
    dst[d] = f;
}

// ---------------- concat [mems_l ; h] -> cat ----------------
__global__ void concat_kernel(const float* __restrict__ mems_l,
                              const float* __restrict__ h,
                              float* __restrict__ cat) {
    int row = blockIdx.x;
    const float4* src = (row < ML * BSZ)
        ? (const float4*)(mems_l + (size_t)row * DM)
        : (const float4*)(h + (size_t)(row - ML * BSZ) * DM);
    float4* dst = (float4*)(cat + (size_t)row * DM);
    dst[threadIdx.x] = src[threadIdx.x];
}

// ---------------- tf32 wmma GEMM ----------------
// C[m,n] = sum_k A[m,k] * B[.]   BROW=0: B is N x K row-major (NT, k contiguous)
//                                BROW=1: B is K x N row-major (NN, n contiguous)
// Block tile 128x128x16, 256 threads (8 warps = 2x4), warp tile 64x32 (4x2 wmma 16x16x8).
// M must be multiple of 128, K multiple of 16, N multiple of 16 (guards handle N<128 tiles).
// Batched over blockIdx.z with z = zn*4 + zb; operand offset = zn*s1 + zb*s2.
template <int BROW>
__global__ void __launch_bounds__(256, 2)
wgemm(const float* __restrict__ A, int lda, size_t sA1, size_t sA2,
      const float* __restrict__ B, int ldb, size_t sB1, size_t sB2,
      float* __restrict__ C, int ldc, size_t sC1, size_t sC2,
      int N, int K) {
    int zn = blockIdx.z >> 2, zb = blockIdx.z & 3;
    const float* Ab = A + (size_t)zn * sA1 + (size_t)zb * sA2;
    const float* Bb = B + (size_t)zn * sB1 + (size_t)zb * sB2;
    float* Cb = C + (size_t)zn * sC1 + (size_t)zb * sC2;
    int m0 = blockIdx.x * 128, n0 = blockIdx.y * 128;
    int tid = threadIdx.x;
    int warp = tid >> 5;
    int wr = warp >> 2, wc = warp & 3;   // warp tile origin (wr*64, wc*32)

    __shared__ __align__(16) float As[128 * 16];
    __shared__ __align__(16) float Bs[128 * 16];

    wmma::fragment<wmma::accumulator, 16, 16, 8, float> acc[4][2];
#pragma unroll
    for (int i = 0; i < 4; i++)
#pragma unroll
        for (int j = 0; j < 2; j++) wmma::fill_fragment(acc[i][j], 0.0f);

    // A loader: 128 rows x 16 floats; thread handles rows arow0 and arow0+64, 4 floats each
    int arow0 = tid >> 2, ac0 = (tid & 3) << 2;
    int arow1 = arow0 + 64;
    // B loader (BROW=0): same pattern over N-rows
    bool g0 = true, g1 = true, gn = true;
    int kr0 = 0, kr1 = 0, nc0 = 0;
    if (BROW == 0) {
        g0 = (n0 + arow0) < N;
        g1 = (n0 + arow1) < N;
    } else {
        kr0 = tid >> 5;            // 0..7
        kr1 = kr0 + 8;
        nc0 = (tid & 31) << 2;     // 0..124
        gn = (n0 + nc0) < N;
    }
    const float4 z4 = {0.f, 0.f, 0.f, 0.f};

    float4 pa0, pa1, pb0, pb1;
    // prefetch k0 = 0
    pa0 = *(const float4*)(Ab + (size_t)(m0 + arow0) * lda + ac0);
    pa1 = *(const float4*)(Ab + (size_t)(m0 + arow1) * lda + ac0);
    if (BROW == 0) {
        pb0 = g0 ? *(const float4*)(Bb + (size_t)(n0 + arow0) * ldb + ac0) : z4;
        pb1 = g1 ? *(const float4*)(Bb + (size_t)(n0 + arow1) * ldb + ac0) : z4;
    } else {
        pb0 = gn ? *(const float4*)(Bb + (size_t)kr0 * ldb + n0 + nc0) : z4;
        pb1 = gn ? *(const float4*)(Bb + (size_t)kr1 * ldb + n0 + nc0) : z4;
    }

    for (int k0 = 0; k0 < K; k0 += 16) {
        *(float4*)&As[arow0 * 16 + ac0] = pa0;
        *(float4*)&As[arow1 * 16 + ac0] = pa1;
        if (BROW == 0) {
            *(float4*)&Bs[arow0 * 16 + ac0] = pb0;
            *(float4*)&Bs[arow1 * 16 + ac0] = pb1;
        } else {
            *(float4*)&Bs[kr0 * 128 + nc0] = pb0;
            *(float4*)&Bs[kr1 * 128 + nc0] = pb1;
        }
        __syncthreads();

        int kn = k0 + 16;
        if (kn < K) {
            pa0 = *(const float4*)(Ab + (size_t)(m0 + arow0) * lda + kn + ac0);
            pa1 = *(const float4*)(Ab + (size_t)(m0 + arow1) * lda + kn + ac0);
            if (BROW == 0) {
                pb0 = g0 ? *(const float4*)(Bb + (size_t)(n0 + arow0) * ldb + kn + ac0) : z4;
                pb1 = g1 ? *(const float4*)(Bb + (size_t)(n0 + arow1) * ldb + kn + ac0) : z4;
            } else {
                pb0 = gn ? *(const float4*)(Bb + (size_t)(kn + kr0) * ldb + n0 + nc0) : z4;
                pb1 = gn ? *(const float4*)(Bb + (size_t)(kn + kr1) * ldb + n0 + nc0) : z4;
            }
        }

#pragma unroll
        for (int ks = 0; ks < 2; ks++) {
            wmma::fragment<wmma::matrix_a, 16, 16, 8, wmma::precision::tf32, wmma::row_major> af[4];
#pragma unroll
            for (int mi = 0; mi < 4; mi++) {
                wmma::load_matrix_sync(af[mi], &As[(wr * 64 + mi * 16) * 16 + ks * 8], 16);
#pragma unroll
                for (int t = 0; t < af[mi].num_elements; t++)
                    af[mi].x[t] = wmma::__float_to_tf32(af[mi].x[t]);
            }
            if (BROW == 0) {
                wmma::fragment<wmma::matrix_b, 16, 16, 8, wmma::precision::tf32, wmma::col_major> bf[2];
#pragma unroll
                for (int ni = 0; ni < 2; ni++) {
                    wmma::load_matrix_sync(bf[ni], &Bs[(wc * 32 + ni * 16) * 16 + ks * 8], 16);
#pragma unroll
                    for (int t = 0; t < bf[ni].num_elements; t++)
                        bf[ni].x[t] = wmma::__float_to_tf32(bf[ni].x[t]);
                }
#pragma unroll
                for (int mi = 0; mi < 4; mi++)
#pragma unroll
                    for (int ni = 0; ni < 2; ni++)
                        wmma::mma_sync(acc[mi][ni], af[mi], bf[ni], acc[mi][ni]);
            } else {
                wmma::fragment<wmma::matrix_b, 16, 16, 8, wmma::precision::tf32, wmma::row_major> bf[2];
#pragma unroll
                for (int ni = 0; ni < 2; ni++) {
                    wmma::load_matrix_sync(bf[ni], &Bs[ks * 8 * 128 + wc * 32 + ni * 16], 128);
#pragma unroll
                    for (int t = 0; t < bf[ni].num_elements; t++)
                        bf[ni].x[t] = wmma::__float_to_tf32(bf[ni].x[t]);
                }
#pragma unroll
                for (int mi = 0; mi < 4; mi++)
#pragma unroll
                    for (int ni = 0; ni < 2; ni++)
                        wmma::mma_sync(acc[mi][ni], af[mi], bf[ni], acc[mi][ni]);
            }
        }
        __syncthreads();
    }

#pragma unroll
    for (int mi = 0; mi < 4; mi++)
#pragma unroll
        for (int ni = 0; ni < 2; ni++) {
            int cn = n0 + wc * 32 + ni * 16;
            if (cn < N)
                wmma::store_matrix_sync(Cb + (size_t)(m0 + wr * 64 + mi * 16) * ldc + cn,
                                        acc[mi][ni], ldc, wmma::mem_row_major);
        }
}

// ---------------- build qc = q + r_w_bias, qr = q + r_r_bias ----------------
// layout: [n*4+b][i][d]  (matches GEMM batch ordering z = n*4 + b)
__global__ void qcqr_kernel(const float* __restrict__ heads,
                            const float* __restrict__ rwb, const float* __restrict__ rrb,
                            float* __restrict__ qc, float* __restrict__ qr) {
    int i = blockIdx.x, b = blockIdx.y;
    int tid = threadIdx.x;   // 256
#pragma unroll
    for (int k = 0; k < 4; k++) {
        int dg = tid + k * 256;            // 0..1023
        int n = dg >> 6, d = dg & 63;
        float q = heads[((size_t)(ML + i) * BSZ + b) * HD3 + n * DH + d];
        size_t o = ((size_t)(n * 4 + b) * QL + i) * DH + d;
        qc[o] = q + rwb[dg];
        qr[o] = q + rrb[dg];
    }
}

// ---------------- fused rel-shift + mask + softmax: S := softmax((S + shift(D))*scale) ----------------
__global__ void __launch_bounds__(256)
softmax_kernel(float* __restrict__ S, const float* __restrict__ D) {
    int i = blockIdx.x;
    int z = blockIdx.y;
    float* row = S + ((size_t)z * QL + i) * KL;
    const float* drow = D + ((size_t)z * QL + i) * KL + (QL - 1 - i);  // drow[j] = D[i, j-i+511]
    int jmax = i + ML;   // inclusive
    __shared__ float sc[KL];
    __shared__ float red[256];
    int tid = threadIdx.x;

    float mx = -1e30f;
    for (int j = tid; j <= jmax; j += 256) {
        float s = (row[j] + drow[j]) * 0.125f;
        sc[j] = s;
        mx = fmaxf(mx, s);
    }
    red[tid] = mx;
    __syncthreads();
    for (int t = 128; t > 0; t >>= 1) {
        if (tid < t) red[tid] = fmaxf(red[tid], red[tid + t]);
        __syncthreads();
    }
    float m = red[0];
    __syncthreads();

    float sum = 0.0f;
    for (int j = tid; j <= jmax; j += 256) {
        float e = expf(sc[j] - m);
        sc[j] = e;
        sum += e;
    }
    red[tid] = sum;
    __syncthreads();
    for (int t = 128; t > 0; t >>= 1) {
        if (tid < t) red[tid] += red[tid + t];
        __syncthreads();
    }
    float inv = 1.0f / red[0];
    __syncthreads();

    for (int j = tid; j <= jmax; j += 256) row[j] = sc[j] * inv;
    for (int j = jmax + 1 + tid; j < KL; j += 256) row[j] = 0.0f;  // masked tail must be 0 for PV GEMM
}

// ---------------- bias (+relu) epilogue ----------------
__global__ void epi_kernel(float* __restrict__ C, const float* __restrict__ bias,
                           int total4, int N, int relu) {
    int idx = blockIdx.x * 256 + threadIdx.x;
    if (idx >= total4) return;
    float4 v = ((float4*)C)[idx];
    int n = (idx * 4) % N;
    v.x += bias[n]; v.y += bias[n + 1]; v.z += bias[n + 2]; v.w += bias[n + 3];
    if (relu) {
        v.x = fmaxf(v.x, 0.f); v.y = fmaxf(v.y, 0.f);
        v.z = fmaxf(v.z, 0.f); v.w = fmaxf(v.w, 0.f);
    }
    ((float4*)C)[idx] = v;
}

// ---------------- fused residual (+bias) + layernorm ----------------
__global__ void __launch_bounds__(256)
ln_kernel(const float* __restrict__ x, const float* __restrict__ y,
          const float* __restrict__ extra,
          const float* __restrict__ g, const float* __restrict__ b,
          float* __restrict__ out) {
    int row = blockIdx.x;
    __shared__ float buf[DM];
    __shared__ float red[256];
    int tid = threadIdx.x;
    float s = 0.0f;
    for (int d = tid; d < DM; d += 256) {
        float v = x[(size_t)row * DM + d] + y[(size_t)row * DM + d];
        if (extra) v += extra[d];
        buf[d] = v;
        s += v;
    }
    red[tid] = s;
    __syncthreads();
    for (int t = 128; t > 0; t >>= 1) {
        if (tid < t) red[tid] += red[tid + t];
        __syncthreads();
    }
    float mu = red[0] * (1.0f / DM);
    __syncthreads();
    float s2 = 0.0f;
    for (int d = tid; d < DM; d += 256) {
        float v = buf[d] - mu;
        s2 += v * v;
    }
    red[tid] = s2;
    __syncthreads();
    for (int t = 128; t > 0; t >>= 1) {
        if (tid < t) red[tid] += red[tid + t];
        __syncthreads();
    }
    float rstd = rsqrtf(red[0] * (1.0f / DM) + 1e-5f);
    __syncthreads();
    for (int d = tid; d < DM; d += 256)
        out[(size_t)row * DM + d] = (buf[d] - mu) * rstd * g[d] + b[d];
}

// ---------------- streaming log-softmax NLL (out_bias folded in) ----------------
__global__ void __launch_bounds__(256)
loss_kernel(const float* __restrict__ logits, const float* __restrict__ ob,
            const int* __restrict__ target, float* __restrict__ out) {
    int row = blockIdx.x;
    const float* lr = logits + (size_t)row * NV;
    __shared__ float red[256];
    int tid = threadIdx.x;
    float m = -1e30f;
    for (int v = tid; v < NV; v += 256) m = fmaxf(m, lr[v] + ob[v]);
    red[tid] = m;
    __syncthreads();
    for (int t = 128; t > 0; t >>= 1) {
        if (tid < t) red[tid] = fmaxf(red[tid], red[tid + t]);
        __syncthreads();
    }
    float M = red[0];
    __syncthreads();
    float s = 0.0f;
    for (int v = tid; v < NV; v += 256) s += expf(lr[v] + ob[v] - M);
    red[tid] = s;
    __syncthreads();
    for (int t = 128; t > 0; t >>= 1) {
        if (tid < t) red[tid] += red[tid + t];
        __syncthreads();
    }
    if (tid == 0) {
        int t = target[row];
        out[row] = -(lr[t] + ob[t] - M - logf(red[0]));
    }
}

// ---------------- driver ----------------
extern "C" void kernel_launch(void* const* d_in, const int* in_sizes, int n_in,
                              void* d_out, int out_size) {
    const int*   data     = (const int*)d_in[0];
    const int*   target   = (const int*)d_in[1];
    const float* mems     = (const float*)d_in[2];
    const float* emb      = (const float*)d_in[3];
    const float* out_bias = (const float*)d_in[4];
    const float* rwb      = (const float*)d_in[5];
    const float* rrb      = (const float*)d_in[6];
    const float* qkv_w    = (const float*)d_in[7];
    const float* r_w      = (const float*)d_in[8];
    const float* o_w      = (const float*)d_in[9];
    const float* ln1g     = (const float*)d_in[10];
    const float* ln1b     = (const float*)d_in[11];
    const float* ff1w     = (const float*)d_in[12];
    const float* ff1b     = (const float*)d_in[13];
    const float* ff2w     = (const float*)d_in[14];
    const float* ff2b     = (const float*)d_in[15];
    const float* ln2g     = (const float*)d_in[16];
    const float* ln2b     = (const float*)d_in[17];
    float* out = (float*)d_out;

    float *p_h, *p_cat, *p_heads, *p_pos, *p_r, *p_qc, *p_qr, *p_S, *p_D,
          *p_av, *p_ao, *p_ffh, *p_ff, *p_logits;
    cudaGetSymbolAddress((void**)&p_h, g_h);
    cudaGetSymbolAddress((void**)&p_cat, g_cat);
    cudaGetSymbolAddress((void**)&p_heads, g_heads);
    cudaGetSymbolAddress((void**)&p_pos, g_pos);
    cudaGetSymbolAddress((void**)&p_r, g_r);
    cudaGetSymbolAddress((void**)&p_qc, g_qc);
    cudaGetSymbolAddress((void**)&p_qr, g_qr);
    cudaGetSymbolAddress((void**)&p_S, g_S);
    cudaGetSymbolAddress((void**)&p_D, g_D);
    cudaGetSymbolAddress((void**)&p_av, g_av);
    cudaGetSymbolAddress((void**)&p_ao, g_ao);
    cudaGetSymbolAddress((void**)&p_ffh, g_ffh);
    cudaGetSymbolAddress((void**)&p_ff, g_ff);
    cudaGetSymbolAddress((void**)&p_logits, g_logits);

    posemb_kernel<<<KL, 512>>>(p_pos);
    embed_kernel<<<QL * BSZ, 256>>>(data, emb, p_h);

    for (int l = 0; l < NL; l++) {
        concat_kernel<<<KL * BSZ, 256>>>(mems + (size_t)l * ML * BSZ * DM, p_h, p_cat);

        // heads = cat @ qkv_w^T : M=4096, N=3072, K=1024
        wgemm<0><<<dim3(32, 24, 1), 256>>>(p_cat, DM, 0, 0,
                                           qkv_w + (size_t)l * HD3 * DM, DM, 0, 0,
                                           p_heads, HD3, 0, 0, HD3, DM);
        // r = pos @ r_w^T : M=1024, N=1024, K=1024
        wgemm<0><<<dim3(8, 8, 1), 256>>>(p_pos, DM, 0, 0,
                                         r_w + (size_t)l * DM * DM, DM, 0, 0,
                                         p_r, DM, 0, 0, DM, DM);
        // qc/qr
        qcqr_kernel<<<dim3(QL, BSZ), 256>>>(p_heads, rwb, rrb, p_qc, p_qr);

        // AC[z] = qc[z] @ K[z]^T : M=512, N=1024, K=64, z = n*4+b
        wgemm<0><<<dim3(4, 8, 64), 256>>>(p_qc, DH, (size_t)4 * QL * DH, (size_t)QL * DH,
                                          p_heads + NH * DH, BSZ * HD3, DH, HD3,
                                          p_S, KL, (size_t)4 * QL * KL, (size_t)QL * KL,
                                          KL, DH);
        // D[z] = qr[z] @ r^T (r slice per head n) : M=512, N=1024, K=64
        wgemm<0><<<dim3(4, 8, 64), 256>>>(p_qr, DH, (size_t)4 * QL * DH, (size_t)QL * DH,
                                          p_r, DM, DH, 0,
                                          p_D, KL, (size_t)4 * QL * KL, (size_t)QL * KL,
                                          KL, DH);
        // softmax with rel-shift + causal mask; S -> P (masked entries zeroed)
        softmax_kernel<<<dim3(QL, BSZ * NH), 256>>>(p_S, p_D);

        // attn_vec[z] = P[z] @ V[z] : M=512, N=64, K=1024 (NN)
        wgemm<1><<<dim3(4, 1, 64), 256>>>(p_S, KL, (size_t)4 * QL * KL, (size_t)QL * KL,
                                          p_heads + 2 * NH * DH, BSZ * HD3, DH, HD3,
                                          p_av, BSZ * DM, DH, DM,
                                          DH, KL);
        // attn_out = attn_vec @ o_w^T : M=2048, N=1024, K=1024
        wgemm<0><<<dim3(16, 8, 1), 256>>>(p_av, DM, 0, 0,
                                          o_w + (size_t)l * DM * DM, DM, 0, 0,
                                          p_ao, DM, 0, 0, DM, DM);
        ln_kernel<<<QL * BSZ, 256>>>(p_h, p_ao, nullptr,
                                     ln1g + l * DM, ln1b + l * DM, p_h);

        // ffh = h @ ff1_w^T : M=2048, N=4096, K=1024; then +bias, relu
        wgemm<0><<<dim3(16, 32, 1), 256>>>(p_h, DM, 0, 0,
                                           ff1w + (size_t)l * DI * DM, DM, 0, 0,
                                           p_ffh, DI, 0, 0, DI, DM);
        epi_kernel<<<(QL * BSZ * DI / 4 + 255) / 256, 256>>>(p_ffh, ff1b + (size_t)l * DI,
                                                             QL * BSZ * DI / 4, DI, 1);
        // ff = ffh @ ff2_w^T : M=2048, N=1024, K=4096 (bias folded into ln)
        wgemm<0><<<dim3(16, 8, 1), 256>>>(p_ffh, DI, 0, 0,
                                          ff2w + (size_t)l * DM * DI, DI, 0, 0,
                                          p_ff, DM, 0, 0, DM, DI);
        ln_kernel<<<QL * BSZ, 256>>>(p_h, p_ff, ff2b + (size_t)l * DM,
                                     ln2g + l * DM, ln2b + l * DM, p_h);
    }

    // logits = h @ emb^T : M=2048, N=32000, K=1024 (out_bias folded into loss)
    wgemm<0><<<dim3(16, 250, 1), 256>>>(p_h, DM, 0, 0,
                                        emb, DM, 0, 0,
                                        p_logits, NV, 0, 0, NV, DM);
    loss_kernel<<<QL * BSZ, 256>>>(p_logits, out_bias, target, out);
}

// round 7
// speedup vs baseline: 6.5110x; 2.7470x over previous
#include <cuda_runtime.h>
#include <cuda_bf16.h>
#include <mma.h>
#include <math.h>

using namespace nvcuda;
typedef __nv_bfloat16 bf16;

// ---------------- problem constants ----------------
#define QL 512
#define ML 512
#define KL 1024          // QL + ML
#define BSZ 4
#define NH 16
#define DH 64
#define DM 1024
#define DI 4096
#define NV 32000
#define NL 6
#define HD3 3072         // 3*NH*DH

// ---------------- fp32 scratch ----------------
__device__ float g_h[(size_t)QL * BSZ * DM];          // residual stream
__device__ float g_heads[(size_t)KL * BSZ * HD3];     // QKV GEMM out
__device__ float g_r[(size_t)KL * DM];
__device__ float g_S[(size_t)BSZ * NH * QL * KL];     // AC
__device__ float g_D[(size_t)BSZ * NH * QL * KL];     // BD (unshifted)
__device__ float g_av[(size_t)QL * BSZ * DM];
__device__ float g_ao[(size_t)QL * BSZ * DM];
__device__ float g_ffh[(size_t)QL * BSZ * DI];
__device__ float g_ff[(size_t)QL * BSZ * DM];
__device__ float g_logits[(size_t)QL * BSZ * NV];

// ---------------- bf16 weight arena ----------------
__device__ bf16 wb_qkv[(size_t)NL * HD3 * DM];
__device__ bf16 wb_r[(size_t)NL * DM * DM];
__device__ bf16 wb_o[(size_t)NL * DM * DM];
__device__ bf16 wb_f1[(size_t)NL * DI * DM];
__device__ bf16 wb_f2[(size_t)NL * DI * DM];
__device__ bf16 wb_emb[(size_t)NV * DM];

// ---------------- bf16 activation buffers ----------------
__device__ bf16 b_cat[(size_t)KL * BSZ * DM];
__device__ bf16 b_heads[(size_t)KL * BSZ * HD3];
__device__ bf16 b_pos[(size_t)KL * DM];
__device__ bf16 b_r[(size_t)KL * DM];
__device__ bf16 b_qc[(size_t)BSZ * NH * QL * DH];
__device__ bf16 b_qr[(size_t)BSZ * NH * QL * DH];
__device__ bf16 b_P[(size_t)BSZ * NH * QL * KL];
__device__ bf16 b_av[(size_t)QL * BSZ * DM];
__device__ bf16 b_h[(size_t)QL * BSZ * DM];
__device__ bf16 b_ffh[(size_t)QL * BSZ * DI];

// ---------------- fp32 -> bf16 bulk convert (n multiple of 8) ----------------
__global__ void f2b_kernel(const float* __restrict__ in, bf16* __restrict__ out, size_t n8) {
    size_t i = (size_t)blockIdx.x * 256 + threadIdx.x;
    if (i >= n8) return;
    const float4* in4 = (const float4*)in;
    float4 a = in4[2 * i], b = in4[2 * i + 1];
    __nv_bfloat162 h0 = __floats2bfloat162_rn(a.x, a.y);
    __nv_bfloat162 h1 = __floats2bfloat162_rn(a.z, a.w);
    __nv_bfloat162 h2 = __floats2bfloat162_rn(b.x, b.y);
    __nv_bfloat162 h3 = __floats2bfloat162_rn(b.z, b.w);
    uint4 u;
    u.x = *(unsigned*)&h0; u.y = *(unsigned*)&h1;
    u.z = *(unsigned*)&h2; u.w = *(unsigned*)&h3;
    ((uint4*)out)[i] = u;
}

// ---------------- positional embedding (bf16) ----------------
__global__ void posemb_kernel(bf16* __restrict__ pos) {
    int p = blockIdx.x;          // 0..KL-1
    int j = threadIdx.x;         // 0..511
    float posv = (float)(KL - 1 - p);
    float inv = expf(-(float)(2 * j) * (9.210340371976184f / 1024.0f));
    float a = posv * inv;
    pos[(size_t)p * DM + j]       = __float2bfloat16(sinf(a));
    pos[(size_t)p * DM + 512 + j] = __float2bfloat16(cosf(a));
}

// ---------------- embedding lookup (fp32 residual) ----------------
__global__ void embed_kernel(const int* __restrict__ data,
                             const float* __restrict__ emb,
                             float* __restrict__ h) {
    int row = blockIdx.x;
    int tok = data[row];
    const float4* src = (const float4*)(emb + (size_t)tok * DM);
    float4* dst = (float4*)(h + (size_t)row * DM);
    int d = threadIdx.x;
    float4 f = src[d];
    f.x *= 32.0f; f.y *= 32.0f; f.z *= 32.0f; f.w *= 32.0f;  // sqrt(1024)
    dst[d] = f;
}

// ---------------- concat [mems_l ; h] -> bf16 cat ----------------
__global__ void concat_kernel(const float* __restrict__ mems_l,
                              const float* __restrict__ h,
                              bf16* __restrict__ cat) {
    int row = blockIdx.x;        // 0..4095
    const float4* src = (row < ML * BSZ)
        ? (const float4*)(mems_l + (size_t)row * DM)
        : (const float4*)(h + (size_t)(row - ML * BSZ) * DM);
    float4 f = src[threadIdx.x];
    __nv_bfloat162 h0 = __floats2bfloat162_rn(f.x, f.y);
    __nv_bfloat162 h1 = __floats2bfloat162_rn(f.z, f.w);
    uint2 u; u.x = *(unsigned*)&h0; u.y = *(unsigned*)&h1;
    ((uint2*)(cat + (size_t)row * DM))[threadIdx.x] = u;
}

// ---------------- bf16 wmma GEMM ----------------
// C[m,n] = sum_k A[m,k]*B[.]; BROW=0: B is NxK row-major; BROW=1: B is KxN row-major.
// Block 128x128x32, 256 threads, 8 warps (2x4), warp tile 64x32 (4x2 m16n16k16).
// M mult of 128, K mult of 32; N guarded per 8-half column group / 16-col store.
// Batched over z = zn*4 + zb.
template <int BROW>
__global__ void __launch_bounds__(256, 2)
wgemmb(const bf16* __restrict__ A, int lda, size_t sA1, size_t sA2,
       const bf16* __restrict__ B, int ldb, size_t sB1, size_t sB2,
       float* __restrict__ C, int ldc, size_t sC1, size_t sC2,
       int N, int K) {
    int zn = blockIdx.z >> 2, zb = blockIdx.z & 3;
    const bf16* Ab = A + (size_t)zn * sA1 + (size_t)zb * sA2;
    const bf16* Bb = B + (size_t)zn * sB1 + (size_t)zb * sB2;
    float* Cb = C + (size_t)zn * sC1 + (size_t)zb * sC2;
    int m0 = blockIdx.x * 128, n0 = blockIdx.y * 128;
    int tid = threadIdx.x;
    int warp = tid >> 5, wr = warp >> 2, wc = warp & 3;

    __shared__ __align__(16) bf16 As[128 * 40];   // 128 rows x 32 (+8 pad)
    __shared__ __align__(16) bf16 Bs[128 * 40];   // BROW=1 uses 32*136 <= 5120

    wmma::fragment<wmma::accumulator, 16, 16, 16, float> acc[4][2];
#pragma unroll
    for (int i = 0; i < 4; i++)
#pragma unroll
        for (int j = 0; j < 2; j++) wmma::fill_fragment(acc[i][j], 0.0f);

    int arow0 = tid >> 2, ac0 = (tid & 3) * 8, arow1 = arow0 + 64;
    int kr0 = 0, kr1 = 0, nc0 = 0;
    bool g0 = true, g1 = true, gn = true;
    if (BROW == 0) {
        g0 = (n0 + arow0) < N;
        g1 = (n0 + arow1) < N;
    } else {
        kr0 = tid >> 4; kr1 = kr0 + 16;
        nc0 = (tid & 15) * 8;
        gn = (n0 + nc0) < N;
    }
    const int4 z4 = {0, 0, 0, 0};

    int4 pa0 = *(const int4*)(Ab + (size_t)(m0 + arow0) * lda + ac0);
    int4 pa1 = *(const int4*)(Ab + (size_t)(m0 + arow1) * lda + ac0);
    int4 pb0, pb1;
    if (BROW == 0) {
        pb0 = g0 ? *(const int4*)(Bb + (size_t)(n0 + arow0) * ldb + ac0) : z4;
        pb1 = g1 ? *(const int4*)(Bb + (size_t)(n0 + arow1) * ldb + ac0) : z4;
    } else {
        pb0 = gn ? *(const int4*)(Bb + (size_t)kr0 * ldb + n0 + nc0) : z4;
        pb1 = gn ? *(const int4*)(Bb + (size_t)kr1 * ldb + n0 + nc0) : z4;
    }

    for (int k0 = 0; k0 < K; k0 += 32) {
        *(int4*)&As[arow0 * 40 + ac0] = pa0;
        *(int4*)&As[arow1 * 40 + ac0] = pa1;
        if (BROW == 0) {
            *(int4*)&Bs[arow0 * 40 + ac0] = pb0;
            *(int4*)&Bs[arow1 * 40 + ac0] = pb1;
        } else {
            *(int4*)&Bs[kr0 * 136 + nc0] = pb0;
            *(int4*)&Bs[kr1 * 136 + nc0] = pb1;
        }
        __syncthreads();

        int kn = k0 + 32;
        if (kn < K) {
            pa0 = *(const int4*)(Ab + (size_t)(m0 + arow0) * lda + kn + ac0);
            pa1 = *(const int4*)(Ab + (size_t)(m0 + arow1) * lda + kn + ac0);
            if (BROW == 0) {
                pb0 = g0 ? *(const int4*)(Bb + (size_t)(n0 + arow0) * ldb + kn + ac0) : z4;
                pb1 = g1 ? *(const int4*)(Bb + (size_t)(n0 + arow1) * ldb + kn + ac0) : z4;
            } else {
                pb0 = gn ? *(const int4*)(Bb + (size_t)(kn + kr0) * ldb + n0 + nc0) : z4;
                pb1 = gn ? *(const int4*)(Bb + (size_t)(kn + kr1) * ldb + n0 + nc0) : z4;
            }
        }

#pragma unroll
        for (int ks = 0; ks < 2; ks++) {
            wmma::fragment<wmma::matrix_a, 16, 16, 16, bf16, wmma::row_major> af[4];
#pragma unroll
            for (int mi = 0; mi < 4; mi++)
                wmma::load_matrix_sync(af[mi], &As[(wr * 64 + mi * 16) * 40 + ks * 16], 40);
            if (BROW == 0) {
                wmma::fragment<wmma::matrix_b, 16, 16, 16, bf16, wmma::col_major> bf[2];
#pragma unroll
                for (int ni = 0; ni < 2; ni++)
                    wmma::load_matrix_sync(bf[ni], &Bs[(wc * 32 + ni * 16) * 40 + ks * 16], 40);
#pragma unroll
                for (int mi = 0; mi < 4; mi++)
#pragma unroll
                    for (int ni = 0; ni < 2; ni++)
                        wmma::mma_sync(acc[mi][ni], af[mi], bf[ni], acc[mi][ni]);
            } else {
                wmma::fragment<wmma::matrix_b, 16, 16, 16, bf16, wmma::row_major> bf[2];
#pragma unroll
                for (int ni = 0; ni < 2; ni++)
                    wmma::load_matrix_sync(bf[ni], &Bs[ks * 16 * 136 + wc * 32 + ni * 16], 136);
#pragma unroll
                for (int mi = 0; mi < 4; mi++)
#pragma unroll
                    for (int ni = 0; ni < 2; ni++)
                        wmma::mma_sync(acc[mi][ni], af[mi], bf[ni], acc[mi][ni]);
            }
        }
        __syncthreads();
    }

#pragma unroll
    for (int mi = 0; mi < 4; mi++)
#pragma unroll
        for (int ni = 0; ni < 2; ni++) {
            int cn = n0 + wc * 32 + ni * 16;
            if (cn < N)
                wmma::store_matrix_sync(Cb + (size_t)(m0 + wr * 64 + mi * 16) * ldc + cn,
                                        acc[mi][ni], ldc, wmma::mem_row_major);
        }
}

// ---------------- qc = q + r_w_bias, qr = q + r_r_bias (bf16 out) ----------------
__global__ void qcqr_kernel(const float* __restrict__ heads,
                            const float* __restrict__ rwb, const float* __restrict__ rrb,
                            bf16* __restrict__ qc, bf16* __restrict__ qr) {
    int i = blockIdx.x, b = blockIdx.y;
    int tid = threadIdx.x;   // 256
#pragma unroll
    for (int k = 0; k < 4; k++) {
        int dg = tid + k * 256;            // 0..1023
        int n = dg >> 6, d = dg & 63;
        float q = heads[((size_t)(ML + i) * BSZ + b) * HD3 + n * DH + d];
        size_t o = ((size_t)(n * 4 + b) * QL + i) * DH + d;
        qc[o] = __float2bfloat16(q + rwb[dg]);
        qr[o] = __float2bfloat16(q + rrb[dg]);
    }
}

// ---------------- fused rel-shift + mask + softmax -> bf16 P ----------------
__global__ void __launch_bounds__(256)
softmax_kernel(const float* __restrict__ S, const float* __restrict__ D,
               bf16* __restrict__ P) {
    int i = blockIdx.x;
    int z = blockIdx.y;
    const float* row = S + ((size_t)z * QL + i) * KL;
    const float* drow = D + ((size_t)z * QL + i) * KL + (QL - 1 - i);  // drow[j] = D[i, j-i+511]
    bf16* prow = P + ((size_t)z * QL + i) * KL;
    int jmax = i + ML;
    __shared__ float sc[KL];
    __shared__ float red[256];
    int tid = threadIdx.x;

    float mx = -1e30f;
    for (int j = tid; j <= jmax; j += 256) {
        float s = (row[j] + drow[j]) * 0.125f;
        sc[j] = s;
        mx = fmaxf(mx, s);
    }
    red[tid] = mx;
    __syncthreads();
    for (int t = 128; t > 0; t >>= 1) {
        if (tid < t) red[tid] = fmaxf(red[tid], red[tid + t]);
        __syncthreads();
    }
    float m = red[0];
    __syncthreads();

    float sum = 0.0f;
    for (int j = tid; j <= jmax; j += 256) {
        float e = expf(sc[j] - m);
        sc[j] = e;
        sum += e;
    }
    red[tid] = sum;
    __syncthreads();
    for (int t = 128; t > 0; t >>= 1) {
        if (tid < t) red[tid] += red[tid + t];
        __syncthreads();
    }
    float inv = 1.0f / red[0];
    __syncthreads();

    for (int j = tid; j <= jmax; j += 256) prow[j] = __float2bfloat16(sc[j] * inv);
    bf16 zero = __float2bfloat16(0.0f);
    for (int j = jmax + 1 + tid; j < KL; j += 256) prow[j] = zero;  // masked tail -> 0 for PV GEMM
}

// ---------------- bias+relu epilogue, fp32 in -> bf16 out ----------------
__global__ void epi_kernel(const float* __restrict__ C, const float* __restrict__ bias,
                           bf16* __restrict__ O, int total4, int N) {
    int idx = blockIdx.x * 256 + threadIdx.x;
    if (idx >= total4) return;
    float4 v = ((const float4*)C)[idx];
    int n = (idx * 4) % N;
    v.x = fmaxf(v.x + bias[n], 0.f);
    v.y = fmaxf(v.y + bias[n + 1], 0.f);
    v.z = fmaxf(v.z + bias[n + 2], 0.f);
    v.w = fmaxf(v.w + bias[n + 3], 0.f);
    __nv_bfloat162 h0 = __floats2bfloat162_rn(v.x, v.y);
    __nv_bfloat162 h1 = __floats2bfloat162_rn(v.z, v.w);
    uint2 u; u.x = *(unsigned*)&h0; u.y = *(unsigned*)&h1;
    ((uint2*)O)[idx] = u;
}

// ---------------- fused residual (+bias) + layernorm; fp32 + bf16 outputs ----------------
__global__ void __launch_bounds__(256)
ln_kernel(const float* __restrict__ x, const float* __restrict__ y,
          const float* __restrict__ extra,
          const float* __restrict__ g, const float* __restrict__ b,
          float* __restrict__ out, bf16* __restrict__ outb) {
    int row = blockIdx.x;
    __shared__ float buf[DM];
    __shared__ float red[256];
    int tid = threadIdx.x;
    float s = 0.0f;
    for (int d = tid; d < DM; d += 256) {
        float v = x[(size_t)row * DM + d] + y[(size_t)row * DM + d];
        if (extra) v += extra[d];
        buf[d] = v;
        s += v;
    }
    red[tid] = s;
    __syncthreads();
    for (int t = 128; t > 0; t >>= 1) {
        if (tid < t) red[tid] += red[tid + t];
        __syncthreads();
    }
    float mu = red[0] * (1.0f / DM);
    __syncthreads();
    float s2 = 0.0f;
    for (int d = tid; d < DM; d += 256) {
        float v = buf[d] - mu;
        s2 += v * v;
    }
    red[tid] = s2;
    __syncthreads();
    for (int t = 128; t > 0; t >>= 1) {
        if (tid < t) red[tid] += red[tid + t];
        __syncthreads();
    }
    float rstd = rsqrtf(red[0] * (1.0f / DM) + 1e-5f);
    __syncthreads();
    for (int d = tid; d < DM; d += 256) {
        float v = (buf[d] - mu) * rstd * g[d] + b[d];
        out[(size_t)row * DM + d] = v;
        outb[(size_t)row * DM + d] = __float2bfloat16(v);
    }
}

// ---------------- streaming log-softmax NLL (out_bias folded in) ----------------
__global__ void __launch_bounds__(256)
loss_kernel(const float* __restrict__ logits, const float* __restrict__ ob,
            const int* __restrict__ target, float* __restrict__ out) {
    int row = blockIdx.x;
    const float* lr = logits + (size_t)row * NV;
    __shared__ float red[256];
    int tid = threadIdx.x;
    float m = -1e30f;
    for (int v = tid; v < NV; v += 256) m = fmaxf(m, lr[v] + ob[v]);
    red[tid] = m;
    __syncthreads();
    for (int t = 128; t > 0; t >>= 1) {
        if (tid < t) red[tid] = fmaxf(red[tid], red[tid + t]);
        __syncthreads();
    }
    float M = red[0];
    __syncthreads();
    float s = 0.0f;
    for (int v = tid; v < NV; v += 256) s += expf(lr[v] + ob[v] - M);
    red[tid] = s;
    __syncthreads();
    for (int t = 128; t > 0; t >>= 1) {
        if (tid < t) red[tid] += red[tid + t];
        __syncthreads();
    }
    if (tid == 0) {
        int t = target[row];
        out[row] = -(lr[t] + ob[t] - M - logf(red[0]));
    }
}

// ---------------- driver ----------------
static inline void conv(const float* src, bf16* dst, size_t n) {
    size_t n8 = n / 8;
    f2b_kernel<<<(unsigned)((n8 + 255) / 256), 256>>>(src, dst, n8);
}

extern "C" void kernel_launch(void* const* d_in, const int* in_sizes, int n_in,
                              void* d_out, int out_size) {
    const int*   data     = (const int*)d_in[0];
    const int*   target   = (const int*)d_in[1];
    const float* mems     = (const float*)d_in[2];
    const float* emb      = (const float*)d_in[3];
    const float* out_bias = (const float*)d_in[4];
    const float* rwb      = (const float*)d_in[5];
    const float* rrb      = (const float*)d_in[6];
    const float* qkv_w    = (const float*)d_in[7];
    const float* r_w      = (const float*)d_in[8];
    const float* o_w      = (const float*)d_in[9];
    const float* ln1g     = (const float*)d_in[10];
    const float* ln1b     = (const float*)d_in[11];
    const float* ff1w     = (const float*)d_in[12];
    const float* ff1b     = (const float*)d_in[13];
    const float* ff2w     = (const float*)d_in[14];
    const float* ff2b     = (const float*)d_in[15];
    const float* ln2g     = (const float*)d_in[16];
    const float* ln2b     = (const float*)d_in[17];
    float* out = (float*)d_out;

    float *p_h, *p_heads, *p_r, *p_S, *p_D, *p_av, *p_ao, *p_ffh, *p_ff, *p_logits;
    bf16 *q_qkv, *q_r, *q_o, *q_f1, *q_f2, *q_emb;
    bf16 *c_cat, *c_heads, *c_pos, *c_r, *c_qc, *c_qr, *c_P, *c_av, *c_h, *c_ffh;
    cudaGetSymbolAddress((void**)&p_h, g_h);
    cudaGetSymbolAddress((void**)&p_heads, g_heads);
    cudaGetSymbolAddress((void**)&p_r, g_r);
    cudaGetSymbolAddress((void**)&p_S, g_S);
    cudaGetSymbolAddress((void**)&p_D, g_D);
    cudaGetSymbolAddress((void**)&p_av, g_av);
    cudaGetSymbolAddress((void**)&p_ao, g_ao);
    cudaGetSymbolAddress((void**)&p_ffh, g_ffh);
    cudaGetSymbolAddress((void**)&p_ff, g_ff);
    cudaGetSymbolAddress((void**)&p_logits, g_logits);
    cudaGetSymbolAddress((void**)&q_qkv, wb_qkv);
    cudaGetSymbolAddress((void**)&q_r, wb_r);
    cudaGetSymbolAddress((void**)&q_o, wb_o);
    cudaGetSymbolAddress((void**)&q_f1, wb_f1);
    cudaGetSymbolAddress((void**)&q_f2, wb_f2);
    cudaGetSymbolAddress((void**)&q_emb, wb_emb);
    cudaGetSymbolAddress((void**)&c_cat, b_cat);
    cudaGetSymbolAddress((void**)&c_heads, b_heads);
    cudaGetSymbolAddress((void**)&c_pos, b_pos);
    cudaGetSymbolAddress((void**)&c_r, b_r);
    cudaGetSymbolAddress((void**)&c_qc, b_qc);
    cudaGetSymbolAddress((void**)&c_qr, b_qr);
    cudaGetSymbolAddress((void**)&c_P, b_P);
    cudaGetSymbolAddress((void**)&c_av, b_av);
    cudaGetSymbolAddress((void**)&c_h, b_h);
    cudaGetSymbolAddress((void**)&c_ffh, b_ffh);

    // weight conversions (once per launch)
    conv(qkv_w, q_qkv, (size_t)NL * HD3 * DM);
    conv(r_w,   q_r,   (size_t)NL * DM * DM);
    conv(o_w,   q_o,   (size_t)NL * DM * DM);
    conv(ff1w,  q_f1,  (size_t)NL * DI * DM);
    conv(ff2w,  q_f2,  (size_t)NL * DI * DM);
    conv(emb,   q_emb, (size_t)NV * DM);

    posemb_kernel<<<KL, 512>>>(c_pos);
    embed_kernel<<<QL * BSZ, 256>>>(data, emb, p_h);

    for (int l = 0; l < NL; l++) {
        concat_kernel<<<KL * BSZ, 256>>>(mems + (size_t)l * ML * BSZ * DM, p_h, c_cat);

        // heads = cat @ qkv_w^T : M=4096, N=3072, K=1024
        wgemmb<0><<<dim3(32, 24, 1), 256>>>(c_cat, DM, 0, 0,
                                            q_qkv + (size_t)l * HD3 * DM, DM, 0, 0,
                                            p_heads, HD3, 0, 0, HD3, DM);
        conv(p_heads, c_heads, (size_t)KL * BSZ * HD3);
        // r = pos @ r_w^T : M=1024, N=1024, K=1024
        wgemmb<0><<<dim3(8, 8, 1), 256>>>(c_pos, DM, 0, 0,
                                          q_r + (size_t)l * DM * DM, DM, 0, 0,
                                          p_r, DM, 0, 0, DM, DM);
        conv(p_r, c_r, (size_t)KL * DM);
        qcqr_kernel<<<dim3(QL, BSZ), 256>>>(p_heads, rwb, rrb, c_qc, c_qr);

        // AC[z] = qc[z] @ K[z]^T : M=512, N=1024, K=64
        wgemmb<0><<<dim3(4, 8, 64), 256>>>(c_qc, DH, (size_t)4 * QL * DH, (size_t)QL * DH,
                                           c_heads + NH * DH, BSZ * HD3, DH, HD3,
                                           p_S, KL, (size_t)4 * QL * KL, (size_t)QL * KL,
                                           KL, DH);
        // D[z] = qr[z] @ r^T (head slice) : M=512, N=1024, K=64
        wgemmb<0><<<dim3(4, 8, 64), 256>>>(c_qr, DH, (size_t)4 * QL * DH, (size_t)QL * DH,
                                           c_r, DM, DH, 0,
                                           p_D, KL, (size_t)4 * QL * KL, (size_t)QL * KL,
                                           KL, DH);
        softmax_kernel<<<dim3(QL, BSZ * NH), 256>>>(p_S, p_D, c_P);

        // attn_vec[z] = P[z] @ V[z] : M=512, N=64, K=1024 (NN)
        wgemmb<1><<<dim3(4, 1, 64), 256>>>(c_P, KL, (size_t)4 * QL * KL, (size_t)QL * KL,
                                           c_heads + 2 * NH * DH, BSZ * HD3, DH, HD3,
                                           p_av, BSZ * DM, DH, DM,
                                           DH, KL);
        conv(p_av, c_av, (size_t)QL * BSZ * DM);
        // attn_out = attn_vec @ o_w^T : M=2048, N=1024, K=1024
        wgemmb<0><<<dim3(16, 8, 1), 256>>>(c_av, DM, 0, 0,
                                           q_o + (size_t)l * DM * DM, DM, 0, 0,
                                           p_ao, DM, 0, 0, DM, DM);
        ln_kernel<<<QL * BSZ, 256>>>(p_h, p_ao, nullptr,
                                     ln1g + l * DM, ln1b + l * DM, p_h, c_h);

        // ffh = h @ ff1_w^T : M=2048, N=4096, K=1024
        wgemmb<0><<<dim3(16, 32, 1), 256>>>(c_h, DM, 0, 0,
                                            q_f1 + (size_t)l * DI * DM, DM, 0, 0,
                                            p_ffh, DI, 0, 0, DI, DM);
        epi_kernel<<<(QL * BSZ * DI / 4 + 255) / 256, 256>>>(p_ffh, ff1b + (size_t)l * DI,
                                                             c_ffh, QL * BSZ * DI / 4, DI);
        // ff = ffh @ ff2_w^T : M=2048, N=1024, K=4096
        wgemmb<0><<<dim3(16, 8, 1), 256>>>(c_ffh, DI, 0, 0,
                                           q_f2 + (size_t)l * DM * DI, DI, 0, 0,
                                           p_ff, DM, 0, 0, DM, DI);
        ln_kernel<<<QL * BSZ, 256>>>(p_h, p_ff, ff2b + (size_t)l * DM,
                                     ln2g + l * DM, ln2b + l * DM, p_h, c_h);
    }

    // logits = h @ emb^T : M=2048, N=32000, K=1024
    wgemmb<0><<<dim3(16, 250, 1), 256>>>(c_h, DM, 0, 0,
                                         q_emb, DM, 0, 0,
                                         p_logits, NV, 0, 0, NV, DM);
    loss_kernel<<<QL * BSZ, 256>>>(p_logits, out_bias, target, out);
}

// round 11
// speedup vs baseline: 7.9746x; 1.2248x over previous
#include <cuda_runtime.h>
#include <cuda_bf16.h>
#include <mma.h>
#include <math.h>

using namespace nvcuda;
typedef __nv_bfloat16 bf16;

// ---------------- problem constants ----------------
#define QL 512
#define ML 512
#define KL 1024          // QL + ML
#define BSZ 4
#define NH 16
#define DH 64
#define DM 1024
#define DI 4096
#define NV 32000
#define NL 6
#define HD3 3072         // 3*NH*DH

// ---------------- fp32 scratch ----------------
__device__ float g_h[(size_t)QL * BSZ * DM];
__device__ float g_S[(size_t)BSZ * NH * QL * KL];     // AC
__device__ float g_D[(size_t)BSZ * NH * QL * KL];     // BD (unshifted)
__device__ float g_ao[(size_t)QL * BSZ * DM];
__device__ float g_ff[(size_t)QL * BSZ * DM];
__device__ float g_logits[(size_t)QL * BSZ * NV];

// ---------------- bf16 weight arena ----------------
__device__ bf16 wb_qkv[(size_t)NL * HD3 * DM];
__device__ bf16 wb_r[(size_t)NL * DM * DM];
__device__ bf16 wb_o[(size_t)NL * DM * DM];
__device__ bf16 wb_f1[(size_t)NL * DI * DM];
__device__ bf16 wb_f2[(size_t)NL * DI * DM];
__device__ bf16 wb_emb[(size_t)NV * DM];

// ---------------- bf16 activation buffers ----------------
__device__ bf16 b_cat[(size_t)KL * BSZ * DM];
__device__ bf16 b_heads[(size_t)KL * BSZ * HD3];
__device__ bf16 b_pos[(size_t)KL * DM];
__device__ bf16 b_r[(size_t)KL * DM];
__device__ bf16 b_qc[(size_t)BSZ * NH * QL * DH];
__device__ bf16 b_qr[(size_t)BSZ * NH * QL * DH];
__device__ bf16 b_P[(size_t)BSZ * NH * QL * KL];
__device__ bf16 b_av[(size_t)QL * BSZ * DM];
__device__ bf16 b_h[(size_t)QL * BSZ * DM];
__device__ bf16 b_ffh[(size_t)QL * BSZ * DI];

// ---------------- cp.async helpers ----------------
__device__ __forceinline__ void cpa16(bf16* dst, const bf16* src, bool pred) {
    unsigned d = (unsigned)__cvta_generic_to_shared(dst);
    int sz = pred ? 16 : 0;
    asm volatile("cp.async.cg.shared.global [%0], [%1], 16, %2;\n"
                 :: "r"(d), "l"(src), "r"(sz));
}
__device__ __forceinline__ void cpa_commit() {
    asm volatile("cp.async.commit_group;\n" ::: "memory");
}

// ---------------- fp32 -> bf16 bulk convert ----------------
__global__ void f2b_kernel(const float* __restrict__ in, bf16* __restrict__ out, size_t n8) {
    size_t i = (size_t)blockIdx.x * 256 + threadIdx.x;
    if (i >= n8) return;
    const float4* in4 = (const float4*)in;
    float4 a = in4[2 * i], b = in4[2 * i + 1];
    __nv_bfloat162 h0 = __floats2bfloat162_rn(a.x, a.y);
    __nv_bfloat162 h1 = __floats2bfloat162_rn(a.z, a.w);
    __nv_bfloat162 h2 = __floats2bfloat162_rn(b.x, b.y);
    __nv_bfloat162 h3 = __floats2bfloat162_rn(b.z, b.w);
    uint4 u;
    u.x = *(unsigned*)&h0; u.y = *(unsigned*)&h1;
    u.z = *(unsigned*)&h2; u.w = *(unsigned*)&h3;
    ((uint4*)out)[i] = u;
}

// ---------------- positional embedding (bf16) ----------------
__global__ void posemb_kernel(bf16* __restrict__ pos) {
    int p = blockIdx.x;
    int j = threadIdx.x;
    float posv = (float)(KL - 1 - p);
    float inv = expf(-(float)(2 * j) * (9.210340371976184f / 1024.0f));
    float a = posv * inv;
    pos[(size_t)p * DM + j]       = __float2bfloat16(sinf(a));
    pos[(size_t)p * DM + 512 + j] = __float2bfloat16(cosf(a));
}

// ---------------- embedding lookup (fp32 residual) ----------------
__global__ void embed_kernel(const int* __restrict__ data,
                             const float* __restrict__ emb,
                             float* __restrict__ h) {
    int row = blockIdx.x;
    int tok = data[row];
    const float4* src = (const float4*)(emb + (size_t)tok * DM);
    float4* dst = (float4*)(h + (size_t)row * DM);
    int d = threadIdx.x;
    float4 f = src[d];
    f.x *= 32.0f; f.y *= 32.0f; f.z *= 32.0f; f.w *= 32.0f;
    dst[d] = f;
}

// ---------------- concat [mems_l ; h] -> bf16 cat ----------------
__global__ void concat_kernel(const float* __restrict__ mems_l,
                              const float* __restrict__ h,
                              bf16* __restrict__ cat) {
    int row = blockIdx.x;
    const float4* src = (row < ML * BSZ)
        ? (const float4*)(mems_l + (size_t)row * DM)
        : (const float4*)(h + (size_t)(row - ML * BSZ) * DM);
    float4 f = src[threadIdx.x];
    __nv_bfloat162 h0 = __floats2bfloat162_rn(f.x, f.y);
    __nv_bfloat162 h1 = __floats2bfloat162_rn(f.z, f.w);
    uint2 u; u.x = *(unsigned*)&h0; u.y = *(unsigned*)&h1;
    ((uint2*)(cat + (size_t)row * DM))[threadIdx.x] = u;
}

// ---------------- bf16 wmma GEMM, cp.async 2-stage pipeline ----------------
// C[m,n] = sum_k A[m,k]*B[.]; BROW=0: B NxK row-major (NT); BROW=1: B KxN row-major (NN).
// OUT: 0 = fp32 store, 1 = bf16 store, 2 = bf16 store with +bias,relu.
// Block 128x128x32, 256 thr, 8 warps (2x4), warp tile 64x32 (4x2 m16n16k16).
// M mult 128, K mult 32, N mult 8 (guards for partial N tiles). Batch z = zn*4+zb.
template <int BROW, int OUT>
__global__ void __launch_bounds__(256, 2)
wgemmb(const bf16* __restrict__ A, int lda, size_t sA1, size_t sA2,
       const bf16* __restrict__ B, int ldb, size_t sB1, size_t sB2,
       void* __restrict__ Cv, int ldc, size_t sC1, size_t sC2,
       const float* __restrict__ bias, int N, int K) {
    int zn = blockIdx.z >> 2, zb = blockIdx.z & 3;
    const bf16* Ab = A + (size_t)zn * sA1 + (size_t)zb * sA2;
    const bf16* Bb = B + (size_t)zn * sB1 + (size_t)zb * sB2;
    int m0 = blockIdx.x * 128, n0 = blockIdx.y * 128;
    int tid = threadIdx.x;
    int warp = tid >> 5, wr = warp >> 2, wc = warp & 3;
    int lane = tid & 31;

    __shared__ __align__(16) bf16 As[2][128 * 40];   // 128 rows x 32 (+8 pad)
    __shared__ __align__(16) bf16 Bs[2][128 * 40];   // BROW=1: 32 rows x 136

    wmma::fragment<wmma::accumulator, 16, 16, 16, float> acc[4][2];
#pragma unroll
    for (int i = 0; i < 4; i++)
#pragma unroll
        for (int j = 0; j < 2; j++) wmma::fill_fragment(acc[i][j], 0.0f);

    int arow0 = tid >> 2, ac0 = (tid & 3) * 8, arow1 = arow0 + 64;
    int kr0 = 0, kr1 = 0, nc0 = 0;
    bool g0 = true, g1 = true, gn = true;
    if (BROW == 0) {
        g0 = (n0 + arow0) < N;
        g1 = (n0 + arow1) < N;
    } else {
        kr0 = tid >> 4; kr1 = kr0 + 16;
        nc0 = (tid & 15) * 8;
        gn = (n0 + nc0) < N;
    }

    auto load_stage = [&](int st, int k0) {
        cpa16(&As[st][arow0 * 40 + ac0], Ab + (size_t)(m0 + arow0) * lda + k0 + ac0, true);
        cpa16(&As[st][arow1 * 40 + ac0], Ab + (size_t)(m0 + arow1) * lda + k0 + ac0, true);
        if (BROW == 0) {
            cpa16(&Bs[st][arow0 * 40 + ac0], Bb + (size_t)(n0 + arow0) * ldb + k0 + ac0, g0);
            cpa16(&Bs[st][arow1 * 40 + ac0], Bb + (size_t)(n0 + arow1) * ldb + k0 + ac0, g1);
        } else {
            cpa16(&Bs[st][kr0 * 136 + nc0], Bb + (size_t)(k0 + kr0) * ldb + n0 + nc0, gn);
            cpa16(&Bs[st][kr1 * 136 + nc0], Bb + (size_t)(k0 + kr1) * ldb + n0 + nc0, gn);
        }
        cpa_commit();
    };

    int nk = K >> 5;
    load_stage(0, 0);
    for (int i = 0; i < nk; i++) {
        int st = i & 1;
        if (i + 1 < nk) {
            load_stage(st ^ 1, (i + 1) << 5);
            asm volatile("cp.async.wait_group 1;\n" ::: "memory");
        } else {
            asm volatile("cp.async.wait_group 0;\n" ::: "memory");
        }
        __syncthreads();

#pragma unroll
        for (int ks = 0; ks < 2; ks++) {
            wmma::fragment<wmma::matrix_a, 16, 16, 16, bf16, wmma::row_major> af[4];
#pragma unroll
            for (int mi = 0; mi < 4; mi++)
                wmma::load_matrix_sync(af[mi], &As[st][(wr * 64 + mi * 16) * 40 + ks * 16], 40);
            if (BROW == 0) {
                wmma::fragment<wmma::matrix_b, 16, 16, 16, bf16, wmma::col_major> bfr[2];
#pragma unroll
                for (int ni = 0; ni < 2; ni++)
                    wmma::load_matrix_sync(bfr[ni], &Bs[st][(wc * 32 + ni * 16) * 40 + ks * 16], 40);
#pragma unroll
                for (int mi = 0; mi < 4; mi++)
#pragma unroll
                    for (int ni = 0; ni < 2; ni++)
                        wmma::mma_sync(acc[mi][ni], af[mi], bfr[ni], acc[mi][ni]);
            } else {
                wmma::fragment<wmma::matrix_b, 16, 16, 16, bf16, wmma::row_major> bfr[2];
#pragma unroll
                for (int ni = 0; ni < 2; ni++)
                    wmma::load_matrix_sync(bfr[ni], &Bs[st][ks * 16 * 136 + wc * 32 + ni * 16], 136);
#pragma unroll
                for (int mi = 0; mi < 4; mi++)
#pragma unroll
                    for (int ni = 0; ni < 2; ni++)
                        wmma::mma_sync(acc[mi][ni], af[mi], bfr[ni], acc[mi][ni]);
            }
        }
        __syncthreads();
    }

    if (OUT == 0) {
        float* Cb = (float*)Cv + (size_t)zn * sC1 + (size_t)zb * sC2;
#pragma unroll
        for (int mi = 0; mi < 4; mi++)
#pragma unroll
            for (int ni = 0; ni < 2; ni++) {
                int cn = n0 + wc * 32 + ni * 16;
                if (cn < N)
                    wmma::store_matrix_sync(Cb + (size_t)(m0 + wr * 64 + mi * 16) * ldc + cn,
                                            acc[mi][ni], ldc, wmma::mem_row_major);
            }
    } else {
        bf16* Cb = (bf16*)Cv + (size_t)zn * sC1 + (size_t)zb * sC2;
        // 16x20 fp32 staging per warp; ldm=20 floats = 80B (multiple of 16B: WMMA-legal)
        float* wbuf = ((float*)As) + warp * 320;
        int r = lane >> 1, ch = (lane & 1) * 8;
#pragma unroll
        for (int mi = 0; mi < 4; mi++)
#pragma unroll
            for (int ni = 0; ni < 2; ni++) {
                wmma::store_matrix_sync(wbuf, acc[mi][ni], 20, wmma::mem_row_major);
                __syncwarp();
                int gn = n0 + wc * 32 + ni * 16 + ch;
                if (gn < N) {
                    int gm = m0 + wr * 64 + mi * 16 + r;
                    float v[8];
#pragma unroll
                    for (int t = 0; t < 8; t++) v[t] = wbuf[r * 20 + ch + t];
                    if (OUT == 2) {
#pragma unroll
                        for (int t = 0; t < 8; t++) v[t] = fmaxf(v[t] + bias[gn + t], 0.0f);
                    }
                    __nv_bfloat162 h0 = __floats2bfloat162_rn(v[0], v[1]);
                    __nv_bfloat162 h1 = __floats2bfloat162_rn(v[2], v[3]);
                    __nv_bfloat162 h2 = __floats2bfloat162_rn(v[4], v[5]);
                    __nv_bfloat162 h3 = __floats2bfloat162_rn(v[6], v[7]);
                    uint4 u;
                    u.x = *(unsigned*)&h0; u.y = *(unsigned*)&h1;
                    u.z = *(unsigned*)&h2; u.w = *(unsigned*)&h3;
                    *(uint4*)(Cb + (size_t)gm * ldc + gn) = u;
                }
                __syncwarp();
            }
    }
}

// ---------------- qc = q + r_w_bias, qr = q + r_r_bias (bf16 in/out) ----------------
__global__ void qcqr_kernel(const bf16* __restrict__ heads,
                            const float* __restrict__ rwb, const float* __restrict__ rrb,
                            bf16* __restrict__ qc, bf16* __restrict__ qr) {
    int i = blockIdx.x, b = blockIdx.y;
    int tid = threadIdx.x;
#pragma unroll
    for (int k = 0; k < 4; k++) {
        int dg = tid + k * 256;
        int n = dg >> 6, d = dg & 63;
        float q = __bfloat162float(heads[((size_t)(ML + i) * BSZ + b) * HD3 + n * DH + d]);
        size_t o = ((size_t)(n * 4 + b) * QL + i) * DH + d;
        qc[o] = __float2bfloat16(q + rwb[dg]);
        qr[o] = __float2bfloat16(q + rrb[dg]);
    }
}

// ---------------- fused rel-shift + mask + softmax -> bf16 P ----------------
__global__ void __launch_bounds__(256)
softmax_kernel(const float* __restrict__ S, const float* __restrict__ D,
               bf16* __restrict__ P) {
    int i = blockIdx.x;
    int z = blockIdx.y;
    const float* row = S + ((size_t)z * QL + i) * KL;
    const float* drow = D + ((size_t)z * QL + i) * KL + (QL - 1 - i);
    bf16* prow = P + ((size_t)z * QL + i) * KL;
    int jmax = i + ML;
    __shared__ float sc[KL];
    __shared__ float red[256];
    int tid = threadIdx.x;

    float mx = -1e30f;
    for (int j = tid; j <= jmax; j += 256) {
        float s = (row[j] + drow[j]) * 0.125f;
        sc[j] = s;
        mx = fmaxf(mx, s);
    }
    red[tid] = mx;
    __syncthreads();
    for (int t = 128; t > 0; t >>= 1) {
        if (tid < t) red[tid] = fmaxf(red[tid], red[tid + t]);
        __syncthreads();
    }
    float m = red[0];
    __syncthreads();

    float sum = 0.0f;
    for (int j = tid; j <= jmax; j += 256) {
        float e = expf(sc[j] - m);
        sc[j] = e;
        sum += e;
    }
    red[tid] = sum;
    __syncthreads();
    for (int t = 128; t > 0; t >>= 1) {
        if (tid < t) red[tid] += red[tid + t];
        __syncthreads();
    }
    float inv = 1.0f / red[0];
    __syncthreads();

    for (int j = tid; j <= jmax; j += 256) prow[j] = __float2bfloat16(sc[j] * inv);
    bf16 zero = __float2bfloat16(0.0f);
    for (int j = jmax + 1 + tid; j < KL; j += 256) prow[j] = zero;
}

// ---------------- fused residual (+bias) + layernorm; fp32 + bf16 outputs ----------------
__global__ void __launch_bounds__(256)
ln_kernel(const float* __restrict__ x, const float* __restrict__ y,
          const float* __restrict__ extra,
          const float* __restrict__ g, const float* __restrict__ b,
          float* __restrict__ out, bf16* __restrict__ outb) {
    int row = blockIdx.x;
    __shared__ float buf[DM];
    __shared__ float red[256];
    int tid = threadIdx.x;
    float s = 0.0f;
    for (int d = tid; d < DM; d += 256) {
        float v = x[(size_t)row * DM + d] + y[(size_t)row * DM + d];
        if (extra) v += extra[d];
        buf[d] = v;
        s += v;
    }
    red[tid] = s;
    __syncthreads();
    for (int t = 128; t > 0; t >>= 1) {
        if (tid < t) red[tid] += red[tid + t];
        __syncthreads();
    }
    float mu = red[0] * (1.0f / DM);
    __syncthreads();
    float s2 = 0.0f;
    for (int d = tid; d < DM; d += 256) {
        float v = buf[d] - mu;
        s2 += v * v;
    }
    red[tid] = s2;
    __syncthreads();
    for (int t = 128; t > 0; t >>= 1) {
        if (tid < t) red[tid] += red[tid + t];
        __syncthreads();
    }
    float rstd = rsqrtf(red[0] * (1.0f / DM) + 1e-5f);
    __syncthreads();
    for (int d = tid; d < DM; d += 256) {
        float v = (buf[d] - mu) * rstd * g[d] + b[d];
        out[(size_t)row * DM + d] = v;
        outb[(size_t)row * DM + d] = __float2bfloat16(v);
    }
}

// ---------------- single-pass online log-softmax NLL ----------------
__global__ void __launch_bounds__(256)
loss_kernel(const float* __restrict__ logits, const float* __restrict__ ob,
            const int* __restrict__ target, float* __restrict__ out) {
    int row = blockIdx.x;
    const float* lr = logits + (size_t)row * NV;
    __shared__ float mred[256];
    __shared__ float sred[256];
    int tid = threadIdx.x;
    float m = -1e30f, s = 0.0f;
    for (int v = tid; v < NV; v += 256) {
        float x = lr[v] + ob[v];
        if (x > m) { s = s * expf(m - x) + 1.0f; m = x; }
        else        s += expf(x - m);
    }
    mred[tid] = m; sred[tid] = s;
    __syncthreads();
    for (int t = 128; t > 0; t >>= 1) {
        if (tid < t) {
            float ma = mred[tid], mb = mred[tid + t];
            float M = fmaxf(ma, mb);
            sred[tid] = sred[tid] * expf(ma - M) + sred[tid + t] * expf(mb - M);
            mred[tid] = M;
        }
        __syncthreads();
    }
    if (tid == 0) {
        int t = target[row];
        out[row] = -(lr[t] + ob[t] - mred[0] - logf(sred[0]));
    }
}

// ---------------- driver ----------------
static inline void conv(const float* src, bf16* dst, size_t n) {
    size_t n8 = n / 8;
    f2b_kernel<<<(unsigned)((n8 + 255) / 256), 256>>>(src, dst, n8);
}

extern "C" void kernel_launch(void* const* d_in, const int* in_sizes, int n_in,
                              void* d_out, int out_size) {
    const int*   data     = (const int*)d_in[0];
    const int*   target   = (const int*)d_in[1];
    const float* mems     = (const float*)d_in[2];
    const float* emb      = (const float*)d_in[3];
    const float* out_bias = (const float*)d_in[4];
    const float* rwb      = (const float*)d_in[5];
    const float* rrb      = (const float*)d_in[6];
    const float* qkv_w    = (const float*)d_in[7];
    const float* r_w      = (const float*)d_in[8];
    const float* o_w      = (const float*)d_in[9];
    const float* ln1g     = (const float*)d_in[10];
    const float* ln1b     = (const float*)d_in[11];
    const float* ff1w     = (const float*)d_in[12];
    const float* ff1b     = (const float*)d_in[13];
    const float* ff2w     = (const float*)d_in[14];
    const float* ff2b     = (const float*)d_in[15];
    const float* ln2g     = (const float*)d_in[16];
    const float* ln2b     = (const float*)d_in[17];
    float* out = (float*)d_out;

    float *p_h, *p_S, *p_D, *p_ao, *p_ff, *p_logits;
    bf16 *q_qkv, *q_r, *q_o, *q_f1, *q_f2, *q_emb;
    bf16 *c_cat, *c_heads, *c_pos, *c_r, *c_qc, *c_qr, *c_P, *c_av, *c_h, *c_ffh;
    cudaGetSymbolAddress((void**)&p_h, g_h);
    cudaGetSymbolAddress((void**)&p_S, g_S);
    cudaGetSymbolAddress((void**)&p_D, g_D);
    cudaGetSymbolAddress((void**)&p_ao, g_ao);
    cudaGetSymbolAddress((void**)&p_ff, g_ff);
    cudaGetSymbolAddress((void**)&p_logits, g_logits);
    cudaGetSymbolAddress((void**)&q_qkv, wb_qkv);
    cudaGetSymbolAddress((void**)&q_r, wb_r);
    cudaGetSymbolAddress((void**)&q_o, wb_o);
    cudaGetSymbolAddress((void**)&q_f1, wb_f1);
    cudaGetSymbolAddress((void**)&q_f2, wb_f2);
    cudaGetSymbolAddress((void**)&q_emb, wb_emb);
    cudaGetSymbolAddress((void**)&c_cat, b_cat);
    cudaGetSymbolAddress((void**)&c_heads, b_heads);
    cudaGetSymbolAddress((void**)&c_pos, b_pos);
    cudaGetSymbolAddress((void**)&c_r, b_r);
    cudaGetSymbolAddress((void**)&c_qc, b_qc);
    cudaGetSymbolAddress((void**)&c_qr, b_qr);
    cudaGetSymbolAddress((void**)&c_P, b_P);
    cudaGetSymbolAddress((void**)&c_av, b_av);
    cudaGetSymbolAddress((void**)&c_h, b_h);
    cudaGetSymbolAddress((void**)&c_ffh, b_ffh);

    conv(qkv_w, q_qkv, (size_t)NL * HD3 * DM);
    conv(r_w,   q_r,   (size_t)NL * DM * DM);
    conv(o_w,   q_o,   (size_t)NL * DM * DM);
    conv(ff1w,  q_f1,  (size_t)NL * DI * DM);
    conv(ff2w,  q_f2,  (size_t)NL * DI * DM);
    conv(emb,   q_emb, (size_t)NV * DM);

    posemb_kernel<<<KL, 512>>>(c_pos);
    embed_kernel<<<QL * BSZ, 256>>>(data, emb, p_h);

    for (int l = 0; l < NL; l++) {
        concat_kernel<<<KL * BSZ, 256>>>(mems + (size_t)l * ML * BSZ * DM, p_h, c_cat);

        // heads = cat @ qkv_w^T : M=4096, N=3072, K=1024 -> bf16
        wgemmb<0, 1><<<dim3(32, 24, 1), 256>>>(c_cat, DM, 0, 0,
                                               q_qkv + (size_t)l * HD3 * DM, DM, 0, 0,
                                               c_heads, HD3, 0, 0, nullptr, HD3, DM);
        // r = pos @ r_w^T : M=1024, N=1024, K=1024 -> bf16
        wgemmb<0, 1><<<dim3(8, 8, 1), 256>>>(c_pos, DM, 0, 0,
                                             q_r + (size_t)l * DM * DM, DM, 0, 0,
                                             c_r, DM, 0, 0, nullptr, DM, DM);
        qcqr_kernel<<<dim3(QL, BSZ), 256>>>(c_heads, rwb, rrb, c_qc, c_qr);

        // AC[z] = qc[z] @ K[z]^T : M=512, N=1024, K=64 -> fp32
        wgemmb<0, 0><<<dim3(4, 8, 64), 256>>>(c_qc, DH, (size_t)4 * QL * DH, (size_t)QL * DH,
                                              c_heads + NH * DH, BSZ * HD3, DH, HD3,
                                              p_S, KL, (size_t)4 * QL * KL, (size_t)QL * KL,
                                              nullptr, KL, DH);
        // D[z] = qr[z] @ r^T (head slice) : M=512, N=1024, K=64 -> fp32
        wgemmb<0, 0><<<dim3(4, 8, 64), 256>>>(c_qr, DH, (size_t)4 * QL * DH, (size_t)QL * DH,
                                              c_r, DM, DH, 0,
                                              p_D, KL, (size_t)4 * QL * KL, (size_t)QL * KL,
                                              nullptr, KL, DH);
        softmax_kernel<<<dim3(QL, BSZ * NH), 256>>>(p_S, p_D, c_P);

        // attn_vec[z] = P[z] @ V[z] : M=512, N=64, K=1024 (NN) -> bf16
        wgemmb<1, 1><<<dim3(4, 1, 64), 256>>>(c_P, KL, (size_t)4 * QL * KL, (size_t)QL * KL,
                                              c_heads + 2 * NH * DH, BSZ * HD3, DH, HD3,
                                              c_av, BSZ * DM, DH, DM, nullptr,
                                              DH, KL);
        // attn_out = attn_vec @ o_w^T : M=2048, N=1024, K=1024 -> fp32
        wgemmb<0, 0><<<dim3(16, 8, 1), 256>>>(c_av, DM, 0, 0,
                                              q_o + (size_t)l * DM * DM, DM, 0, 0,
                                              p_ao, DM, 0, 0, nullptr, DM, DM);
        ln_kernel<<<QL * BSZ, 256>>>(p_h, p_ao, nullptr,
                                     ln1g + l * DM, ln1b + l * DM, p_h, c_h);

        // ffh = relu(h @ ff1_w^T + b) : M=2048, N=4096, K=1024 -> bf16 fused epilogue
        wgemmb<0, 2><<<dim3(16, 32, 1), 256>>>(c_h, DM, 0, 0,
                                               q_f1 + (size_t)l * DI * DM, DM, 0, 0,
                                               c_ffh, DI, 0, 0, ff1b + (size_t)l * DI, DI, DM);
        // ff = ffh @ ff2_w^T : M=2048, N=1024, K=4096 -> fp32
        wgemmb<0, 0><<<dim3(16, 8, 1), 256>>>(c_ffh, DI, 0, 0,
                                              q_f2 + (size_t)l * DM * DI, DI, 0, 0,
                                              p_ff, DM, 0, 0, nullptr, DM, DI);
        ln_kernel<<<QL * BSZ, 256>>>(p_h, p_ff, ff2b + (size_t)l * DM,
                                     ln2g + l * DM, ln2b + l * DM, p_h, c_h);
    }

    // logits = h @ emb^T : M=2048, N=32000, K=1024 -> fp32
    wgemmb<0, 0><<<dim3(16, 250, 1), 256>>>(c_h, DM, 0, 0,
                                            q_emb, DM, 0, 0,
                                            p_logits, NV, 0, 0, nullptr, NV, DM);
    loss_kernel<<<QL * BSZ, 256>>>(p_logits, out_bias, target, out);
}